// round 12
// baseline (speedup 1.0000x reference)
#include <cuda_runtime.h>
#include <cuda_bf16.h>

#define GD 128
#define RB 66                         // brick coords 0..65 cover x0 in [-2..128]
#define BRICKS (RB * RB * RB)         // 287,496 bricks per replica
#define TOTAL_BRICKS (8 * BRICKS)     // 8 parity replicas
#define CELLS (GD * GD * GD)
// Each brick = 2x2x2 cells as bf16 = 16 bytes.
// Zero-initialized at load; huber_zero_kernel re-zeroes every slot it reads,
// so the read-region invariant holds across graph replays. Padding slots may
// accumulate garbage but are never read.
__device__ uint4 g_rep[TOTAL_BRICKS];

__device__ __forceinline__ unsigned pack_bf16x2(float lo, float hi) {
    unsigned u;
    asm("cvt.rn.bf16x2.f32 %0, %1, %2;" : "=r"(u) : "f"(hi), "f"(lo));
    return u;
}

__device__ __forceinline__ void red_add_v4_bf16x2(void* addr, unsigned a,
                                                  unsigned b, unsigned c,
                                                  unsigned d) {
    asm volatile("red.global.add.noftz.v4.bf16x2 [%0], {%1, %2, %3, %4};"
                 :: "l"(addr), "r"(a), "r"(b), "r"(c), "r"(d) : "memory");
}

// ---------------------------------------------------------------------------
// One splat = ONE v4.bf16x2 red: replica (x0&1,y0&1,z0&1) makes the 2x2x2
// corner cube one aligned 16B brick. Lane idx = lz*4 + ly*2 + lx.
// ---------------------------------------------------------------------------
__device__ __forceinline__ void splat_one(float cx, float cy, float cz,
                                          float sign) {
    const float x = fmaf(cx, 64.0f, 63.5f);   // ((c+1)*128-1)/2
    const float y = fmaf(cy, 64.0f, 63.5f);
    const float z = fmaf(cz, 64.0f, 63.5f);

    const float x0f = floorf(x), y0f = floorf(y), z0f = floorf(z);
    const float fx = x - x0f, fy = y - y0f, fz = z - z0f;
    int x0 = (int)x0f, y0 = (int)y0f, z0 = (int)z0f;
    // Far-out points clamp into the padded range; OOB corners land in padding
    // slots the huber gather never reads (and never zeroes — harmless).
    x0 = max(-2, min(128, x0));
    y0 = max(-2, min(128, y0));
    z0 = max(-2, min(128, z0));

    const float wx0 = 1.0f - fx, wx1 = fx;
    const float wy0 = 1.0f - fy, wy1 = fy;
    const float wz0 = (1.0f - fz) * sign, wz1 = fz * sign;

    const int sx = x0 & 1, sy = y0 & 1, sz = z0 & 1;
    const int bx = (x0 + sx + 2) >> 1;
    const int by = (y0 + sy + 2) >> 1;
    const int bz = (z0 + sz + 2) >> 1;
    const int rep = (sz << 2) | (sy << 1) | sx;

    uint4* addr = g_rep + (size_t)rep * BRICKS
                + ((size_t)bz * RB + by) * RB + bx;

    const float a00 = wx0 * wy0, a10 = wx1 * wy0;
    const float a01 = wx0 * wy1, a11 = wx1 * wy1;

    red_add_v4_bf16x2(addr,
        pack_bf16x2(a00 * wz0, a10 * wz0),
        pack_bf16x2(a01 * wz0, a11 * wz0),
        pack_bf16x2(a00 * wz1, a10 * wz1),
        pack_bf16x2(a01 * wz1, a11 * wz1));
}

// ---------------------------------------------------------------------------
// Splat: ONE point per thread (proven best occupancy/latency-hiding shape).
// ---------------------------------------------------------------------------
__global__ void splat_kernel(const float* __restrict__ pred,
                             const float* __restrict__ gt,
                             const float* __restrict__ coords,
                             int N, float* __restrict__ out) {
    const int p = blockIdx.x * blockDim.x + threadIdx.x;
    if (p == 0) *out = 0.f;      // huber (next kernel) accumulates into out
    if (p >= N) return;

    const float cx = coords[3 * p + 0];
    const float cy = coords[3 * p + 1];
    const float cz = coords[3 * p + 2];
    const float px = pred[3 * p + 0];
    const float py = pred[3 * p + 1];
    const float pz = pred[3 * p + 2];
    const float gx = gt[3 * p + 0];
    const float gy = gt[3 * p + 1];
    const float gz = gt[3 * p + 2];

    splat_one(cx + px, cy + py, cz + pz,  1.0f);
    splat_one(cx + gx, cy + gy, cz + gz, -1.0f);
}

// ---------------------------------------------------------------------------
// Fused huber + zero, spill-free streaming form. 8 cells (one aligned
// x-octet) per thread; per replica: load 4 (sx=0) or 5 (sx=1) consecutive
// bf16x2 uints, __syncwarp (shared sx=1 boundary uints are read only by
// x-adjacent threads in the SAME warp -- a warp spans 2 complete 16-thread
// rows), store zeros back, accumulate. No address/value arrays survive
// across replicas -> no spills.
// ---------------------------------------------------------------------------
#define HUB_THREADS 256

__global__ void huber_zero_kernel(float* __restrict__ out) {
    unsigned* __restrict__ gu = reinterpret_cast<unsigned*>(g_rep);
    const int t = blockIdx.x * HUB_THREADS + threadIdx.x;
    const int cell0 = t * 8;
    const int xx0 = cell0 & 127;            // even multiple of 8
    const int yy  = (cell0 >> 7) & 127;
    const int zz  = cell0 >> 14;
    const int B0  = (xx0 + 2) >> 1;

    float vc[8];
    #pragma unroll
    for (int j = 0; j < 8; ++j) vc[j] = 0.f;

    #pragma unroll
    for (int rep = 0; rep < 8; ++rep) {
        const int sx = rep & 1, sy = (rep >> 1) & 1, sz = rep >> 2;
        const int ly = (yy ^ sy) & 1;
        const int lz = (zz ^ sz) & 1;
        const int by = (yy - ly + sy + 2) >> 1;
        const int bz = (zz - lz + sz + 2) >> 1;
        const int off = (lz << 1) | ly;     // uint within brick
        const size_t base = ((size_t)rep * BRICKS
                           + ((size_t)bz * RB + by) * RB + B0) * 4 + off;

        unsigned u0 = gu[base +  0];
        unsigned u1 = gu[base +  4];
        unsigned u2 = gu[base +  8];
        unsigned u3 = gu[base + 12];
        unsigned u4 = 0;
        if (sx) u4 = gu[base + 16];

        // Order: both x-adjacent readers of a shared boundary uint are in
        // this warp and have loaded it; now zeroing is safe.
        __syncwarp();

        gu[base +  0] = 0u;
        gu[base +  4] = 0u;
        gu[base +  8] = 0u;
        gu[base + 12] = 0u;
        if (sx) gu[base + 16] = 0u;

        const __nv_bfloat162 b0 = *reinterpret_cast<const __nv_bfloat162*>(&u0);
        const __nv_bfloat162 b1 = *reinterpret_cast<const __nv_bfloat162*>(&u1);
        const __nv_bfloat162 b2 = *reinterpret_cast<const __nv_bfloat162*>(&u2);
        const __nv_bfloat162 b3 = *reinterpret_cast<const __nv_bfloat162*>(&u3);
        const __nv_bfloat162 b4 = *reinterpret_cast<const __nv_bfloat162*>(&u4);

        if (sx == 0) {
            // cell j: uint j>>1; even j -> lo, odd j -> hi
            vc[0] += __bfloat162float(b0.x);
            vc[1] += __bfloat162float(b0.y);
            vc[2] += __bfloat162float(b1.x);
            vc[3] += __bfloat162float(b1.y);
            vc[4] += __bfloat162float(b2.x);
            vc[5] += __bfloat162float(b2.y);
            vc[6] += __bfloat162float(b3.x);
            vc[7] += __bfloat162float(b3.y);
        } else {
            // cell j even -> hi of uint j/2; odd -> lo of uint (j+1)/2
            vc[0] += __bfloat162float(b0.y);
            vc[1] += __bfloat162float(b1.x);
            vc[2] += __bfloat162float(b1.y);
            vc[3] += __bfloat162float(b2.x);
            vc[4] += __bfloat162float(b2.y);
            vc[5] += __bfloat162float(b3.x);
            vc[6] += __bfloat162float(b3.y);
            vc[7] += __bfloat162float(b4.x);
        }
    }

    float s = 0.f;
    #pragma unroll
    for (int j = 0; j < 8; ++j) {
        const float a = fabsf(vc[j]);
        s += (a <= 1.f) ? 0.5f * vc[j] * vc[j] : a - 0.5f;
    }

    #pragma unroll
    for (int o = 16; o; o >>= 1) s += __shfl_xor_sync(0xFFFFFFFFu, s, o);

    __shared__ float smem[8];
    const int lane = threadIdx.x & 31;
    const int warp = threadIdx.x >> 5;
    if (lane == 0) smem[warp] = s;
    __syncthreads();

    if (warp == 0) {
        s = (lane < (HUB_THREADS >> 5)) ? smem[lane] : 0.f;
        #pragma unroll
        for (int o = 4; o; o >>= 1) s += __shfl_xor_sync(0xFFFFFFFFu, s, o);
        if (lane == 0) atomicAdd(out, s);
    }
}

// ---------------------------------------------------------------------------
// Launch: splat -> fused huber+zero
// ---------------------------------------------------------------------------
extern "C" void kernel_launch(void* const* d_in, const int* in_sizes, int n_in,
                              void* d_out, int out_size) {
    const float* pred   = (const float*)d_in[0];  // registration_pred [1,N,3]
    const float* gt     = (const float*)d_in[1];  // registration_gt   [1,N,3]
    const float* coords = (const float*)d_in[2];  // coords            [1,N,3]
    float* out = (float*)d_out;

    const int N = in_sizes[0] / 3;

    {   // splat: one thread per point (pred +1, gt -1); also zeroes *out
        const int threads = 256;
        splat_kernel<<<(N + threads - 1) / threads, threads>>>(
            pred, gt, coords, N, out);
    }
    {   // fused huber gather + reduction + grid re-zero: 8 cells/thread
        const int nt = CELLS / 8;                  // 262,144 threads
        huber_zero_kernel<<<nt / HUB_THREADS, HUB_THREADS>>>(out);
    }
}

// round 13
// speedup vs baseline: 1.3285x; 1.3285x over previous
#include <cuda_runtime.h>
#include <cuda_bf16.h>

#define GD 128
#define RB 66                         // brick coords 0..65 cover x0 in [-2..128]
#define BRICKS (RB * RB * RB)         // 287,496 bricks per replica
#define TOTAL_BRICKS (8 * BRICKS)     // 8 parity replicas
#define CELLS (GD * GD * GD)
// Each brick = 2x2x2 cells as bf16 = 16 bytes.
// Zero-initialized at load; huber_zero_kernel re-zeroes every slot it reads,
// so the read-region invariant holds across graph replays. Padding slots may
// accumulate garbage but are never read.
__device__ uint4 g_rep[TOTAL_BRICKS];

__device__ __forceinline__ unsigned pack_bf16x2(float lo, float hi) {
    unsigned u;
    asm("cvt.rn.bf16x2.f32 %0, %1, %2;" : "=r"(u) : "f"(hi), "f"(lo));
    return u;
}

__device__ __forceinline__ void red_add_v4_bf16x2(void* addr, unsigned a,
                                                  unsigned b, unsigned c,
                                                  unsigned d) {
    asm volatile("red.global.add.noftz.v4.bf16x2 [%0], {%1, %2, %3, %4};"
                 :: "l"(addr), "r"(a), "r"(b), "r"(c), "r"(d) : "memory");
}

// ---------------------------------------------------------------------------
// One splat = ONE v4.bf16x2 red: replica (x0&1,y0&1,z0&1) makes the 2x2x2
// corner cube one aligned 16B brick. Lane idx = lz*4 + ly*2 + lx.
// ---------------------------------------------------------------------------
__device__ __forceinline__ void splat_one(float cx, float cy, float cz,
                                          float sign) {
    const float x = fmaf(cx, 64.0f, 63.5f);   // ((c+1)*128-1)/2
    const float y = fmaf(cy, 64.0f, 63.5f);
    const float z = fmaf(cz, 64.0f, 63.5f);

    const float x0f = floorf(x), y0f = floorf(y), z0f = floorf(z);
    const float fx = x - x0f, fy = y - y0f, fz = z - z0f;
    int x0 = (int)x0f, y0 = (int)y0f, z0 = (int)z0f;
    // Far-out points clamp into the padded range; OOB corners land in padding
    // slots the huber gather never reads (and never zeroes — harmless).
    x0 = max(-2, min(128, x0));
    y0 = max(-2, min(128, y0));
    z0 = max(-2, min(128, z0));

    const float wx0 = 1.0f - fx, wx1 = fx;
    const float wy0 = 1.0f - fy, wy1 = fy;
    const float wz0 = (1.0f - fz) * sign, wz1 = fz * sign;

    const int sx = x0 & 1, sy = y0 & 1, sz = z0 & 1;
    const int bx = (x0 + sx + 2) >> 1;
    const int by = (y0 + sy + 2) >> 1;
    const int bz = (z0 + sz + 2) >> 1;
    const int rep = (sz << 2) | (sy << 1) | sx;

    uint4* addr = g_rep + (size_t)rep * BRICKS
                + ((size_t)bz * RB + by) * RB + bx;

    const float a00 = wx0 * wy0, a10 = wx1 * wy0;
    const float a01 = wx0 * wy1, a11 = wx1 * wy1;

    red_add_v4_bf16x2(addr,
        pack_bf16x2(a00 * wz0, a10 * wz0),
        pack_bf16x2(a01 * wz0, a11 * wz0),
        pack_bf16x2(a00 * wz1, a10 * wz1),
        pack_bf16x2(a01 * wz1, a11 * wz1));
}

// ---------------------------------------------------------------------------
// Splat: ONE point per thread (proven best occupancy/latency-hiding shape).
// ---------------------------------------------------------------------------
__global__ void splat_kernel(const float* __restrict__ pred,
                             const float* __restrict__ gt,
                             const float* __restrict__ coords,
                             int N, float* __restrict__ out) {
    const int p = blockIdx.x * blockDim.x + threadIdx.x;
    if (p == 0) *out = 0.f;      // huber (next kernel) accumulates into out
    if (p >= N) return;

    const float cx = coords[3 * p + 0];
    const float cy = coords[3 * p + 1];
    const float cz = coords[3 * p + 2];
    const float px = pred[3 * p + 0];
    const float py = pred[3 * p + 1];
    const float pz = pred[3 * p + 2];
    const float gx = gt[3 * p + 0];
    const float gy = gt[3 * p + 1];
    const float gz = gt[3 * p + 2];

    splat_one(cx + px, cy + py, cz + pz,  1.0f);
    splat_one(cx + gx, cy + gy, cz + gz, -1.0f);
}

// ---------------------------------------------------------------------------
// Fused huber + zero, decoupled phases. 8 cells (one aligned x-octet) per
// thread. Phase A: per replica load 4 (sx=0) / 5 (sx=1) consecutive bf16x2
// uints and accumulate immediately into vc[8] (no stores -> loads pipeline,
// no spills). Phase B: reduction. Phase C (after __syncthreads): recompute
// the same addresses and store zeros (fire-and-forget STGs; the only shared
// uints are sx=1 boundaries between x-adjacent threads of the same warp, and
// both store identical 0 -> deterministic).
// ---------------------------------------------------------------------------
#define HUB_THREADS 128

__global__ void huber_zero_kernel(float* __restrict__ out) {
    unsigned* __restrict__ gu = reinterpret_cast<unsigned*>(g_rep);
    const int t = blockIdx.x * HUB_THREADS + threadIdx.x;
    const int cell0 = t * 8;
    const int xx0 = cell0 & 127;            // even multiple of 8
    const int yy  = (cell0 >> 7) & 127;
    const int zz  = cell0 >> 14;
    const int B0  = (xx0 + 2) >> 1;

    float vc[8];
    #pragma unroll
    for (int j = 0; j < 8; ++j) vc[j] = 0.f;

    // ---- Phase A: gather + accumulate (loads only) ----
    #pragma unroll
    for (int rep = 0; rep < 8; ++rep) {
        const int sx = rep & 1, sy = (rep >> 1) & 1, sz = rep >> 2;
        const int ly = (yy ^ sy) & 1;
        const int lz = (zz ^ sz) & 1;
        const int by = (yy - ly + sy + 2) >> 1;
        const int bz = (zz - lz + sz + 2) >> 1;
        const int off = (lz << 1) | ly;     // uint within brick
        const size_t base = ((size_t)rep * BRICKS
                           + ((size_t)bz * RB + by) * RB + B0) * 4 + off;

        const unsigned u0 = gu[base +  0];
        const unsigned u1 = gu[base +  4];
        const unsigned u2 = gu[base +  8];
        const unsigned u3 = gu[base + 12];
        const unsigned u4 = sx ? gu[base + 16] : 0u;

        const __nv_bfloat162 b0 = *reinterpret_cast<const __nv_bfloat162*>(&u0);
        const __nv_bfloat162 b1 = *reinterpret_cast<const __nv_bfloat162*>(&u1);
        const __nv_bfloat162 b2 = *reinterpret_cast<const __nv_bfloat162*>(&u2);
        const __nv_bfloat162 b3 = *reinterpret_cast<const __nv_bfloat162*>(&u3);
        const __nv_bfloat162 b4 = *reinterpret_cast<const __nv_bfloat162*>(&u4);

        if (sx == 0) {
            vc[0] += __bfloat162float(b0.x);
            vc[1] += __bfloat162float(b0.y);
            vc[2] += __bfloat162float(b1.x);
            vc[3] += __bfloat162float(b1.y);
            vc[4] += __bfloat162float(b2.x);
            vc[5] += __bfloat162float(b2.y);
            vc[6] += __bfloat162float(b3.x);
            vc[7] += __bfloat162float(b3.y);
        } else {
            vc[0] += __bfloat162float(b0.y);
            vc[1] += __bfloat162float(b1.x);
            vc[2] += __bfloat162float(b1.y);
            vc[3] += __bfloat162float(b2.x);
            vc[4] += __bfloat162float(b2.y);
            vc[5] += __bfloat162float(b3.x);
            vc[6] += __bfloat162float(b3.y);
            vc[7] += __bfloat162float(b4.x);
        }
    }

    // ---- Phase B: huber + reduction ----
    float s = 0.f;
    #pragma unroll
    for (int j = 0; j < 8; ++j) {
        const float a = fabsf(vc[j]);
        s += (a <= 1.f) ? 0.5f * vc[j] * vc[j] : a - 0.5f;
    }

    #pragma unroll
    for (int o = 16; o; o >>= 1) s += __shfl_xor_sync(0xFFFFFFFFu, s, o);

    __shared__ float smem[4];
    const int lane = threadIdx.x & 31;
    const int warp = threadIdx.x >> 5;
    if (lane == 0) smem[warp] = s;
    __syncthreads();

    if (warp == 0 && lane == 0) {
        float tot = smem[0] + smem[1] + smem[2] + smem[3];
        atomicAdd(out, tot);
    }

    // ---- Phase C: zero everything this thread read ----
    __syncthreads();   // all loads in this block have been consumed

    #pragma unroll
    for (int rep = 0; rep < 8; ++rep) {
        const int sx = rep & 1, sy = (rep >> 1) & 1, sz = rep >> 2;
        const int ly = (yy ^ sy) & 1;
        const int lz = (zz ^ sz) & 1;
        const int by = (yy - ly + sy + 2) >> 1;
        const int bz = (zz - lz + sz + 2) >> 1;
        const int off = (lz << 1) | ly;
        const size_t base = ((size_t)rep * BRICKS
                           + ((size_t)bz * RB + by) * RB + B0) * 4 + off;

        gu[base +  0] = 0u;
        gu[base +  4] = 0u;
        gu[base +  8] = 0u;
        gu[base + 12] = 0u;
        if (sx) gu[base + 16] = 0u;
    }
}

// ---------------------------------------------------------------------------
// Launch: splat -> fused huber+zero
// ---------------------------------------------------------------------------
extern "C" void kernel_launch(void* const* d_in, const int* in_sizes, int n_in,
                              void* d_out, int out_size) {
    const float* pred   = (const float*)d_in[0];  // registration_pred [1,N,3]
    const float* gt     = (const float*)d_in[1];  // registration_gt   [1,N,3]
    const float* coords = (const float*)d_in[2];  // coords            [1,N,3]
    float* out = (float*)d_out;

    const int N = in_sizes[0] / 3;

    {   // splat: one thread per point (pred +1, gt -1); also zeroes *out
        const int threads = 256;
        splat_kernel<<<(N + threads - 1) / threads, threads>>>(
            pred, gt, coords, N, out);
    }
    {   // fused huber gather + reduction + grid re-zero: 8 cells/thread
        const int nt = CELLS / 8;                  // 262,144 threads
        huber_zero_kernel<<<nt / HUB_THREADS, HUB_THREADS>>>(out);
    }
}

// round 14
// speedup vs baseline: 1.5636x; 1.1770x over previous
#include <cuda_runtime.h>
#include <cuda_bf16.h>

#define GD 128
#define RB 66                         // brick coords 0..65 cover x0 in [-2..128]
#define BRICKS (RB * RB * RB)         // 287,496 bricks per replica
#define TOTAL_BRICKS (8 * BRICKS)     // 8 parity replicas
#define CELLS (GD * GD * GD)
// Each brick = 2x2x2 cells as bf16 = 16 bytes.
// Zero-initialized at load; huber_zero_kernel re-zeroes every uint it reads
// (single-owner rule), so the read-region invariant holds across graph
// replays. Padding uints may accumulate garbage but are never read.
__device__ uint4 g_rep[TOTAL_BRICKS];

__device__ __forceinline__ unsigned pack_bf16x2(float lo, float hi) {
    unsigned u;
    asm("cvt.rn.bf16x2.f32 %0, %1, %2;" : "=r"(u) : "f"(hi), "f"(lo));
    return u;
}

__device__ __forceinline__ void red_add_v4_bf16x2(void* addr, unsigned a,
                                                  unsigned b, unsigned c,
                                                  unsigned d) {
    asm volatile("red.global.add.noftz.v4.bf16x2 [%0], {%1, %2, %3, %4};"
                 :: "l"(addr), "r"(a), "r"(b), "r"(c), "r"(d) : "memory");
}

// ---------------------------------------------------------------------------
// One splat = ONE v4.bf16x2 red: replica (x0&1,y0&1,z0&1) makes the 2x2x2
// corner cube one aligned 16B brick. Lane idx = lz*4 + ly*2 + lx.
// ---------------------------------------------------------------------------
__device__ __forceinline__ void splat_one(float cx, float cy, float cz,
                                          float sign) {
    const float x = fmaf(cx, 64.0f, 63.5f);   // ((c+1)*128-1)/2
    const float y = fmaf(cy, 64.0f, 63.5f);
    const float z = fmaf(cz, 64.0f, 63.5f);

    const float x0f = floorf(x), y0f = floorf(y), z0f = floorf(z);
    const float fx = x - x0f, fy = y - y0f, fz = z - z0f;
    int x0 = (int)x0f, y0 = (int)y0f, z0 = (int)z0f;
    // Far-out points clamp into the padded range; OOB corners land in padding
    // slots the huber gather never reads (and never zeroes — harmless).
    x0 = max(-2, min(128, x0));
    y0 = max(-2, min(128, y0));
    z0 = max(-2, min(128, z0));

    const float wx0 = 1.0f - fx, wx1 = fx;
    const float wy0 = 1.0f - fy, wy1 = fy;
    const float wz0 = (1.0f - fz) * sign, wz1 = fz * sign;

    const int sx = x0 & 1, sy = y0 & 1, sz = z0 & 1;
    const int bx = (x0 + sx + 2) >> 1;
    const int by = (y0 + sy + 2) >> 1;
    const int bz = (z0 + sz + 2) >> 1;
    const int rep = (sz << 2) | (sy << 1) | sx;

    uint4* addr = g_rep + (size_t)rep * BRICKS
                + ((size_t)bz * RB + by) * RB + bx;

    const float a00 = wx0 * wy0, a10 = wx1 * wy0;
    const float a01 = wx0 * wy1, a11 = wx1 * wy1;

    red_add_v4_bf16x2(addr,
        pack_bf16x2(a00 * wz0, a10 * wz0),
        pack_bf16x2(a01 * wz0, a11 * wz0),
        pack_bf16x2(a00 * wz1, a10 * wz1),
        pack_bf16x2(a01 * wz1, a11 * wz1));
}

// ---------------------------------------------------------------------------
// Splat: ONE point per thread (proven best occupancy/latency-hiding shape).
// ---------------------------------------------------------------------------
__global__ void splat_kernel(const float* __restrict__ pred,
                             const float* __restrict__ gt,
                             const float* __restrict__ coords,
                             int N, float* __restrict__ out) {
    const int p = blockIdx.x * blockDim.x + threadIdx.x;
    if (p == 0) *out = 0.f;      // huber (next kernel) accumulates into out
    if (p >= N) return;

    const float cx = coords[3 * p + 0];
    const float cy = coords[3 * p + 1];
    const float cz = coords[3 * p + 2];
    const float px = pred[3 * p + 0];
    const float py = pred[3 * p + 1];
    const float pz = pred[3 * p + 2];
    const float gx = gt[3 * p + 0];
    const float gy = gt[3 * p + 1];
    const float gz = gt[3 * p + 2];

    splat_one(cx + px, cy + py, cz + pz,  1.0f);
    splat_one(cx + gx, cy + gy, cz + gz, -1.0f);
}

// ---------------------------------------------------------------------------
// Fused huber + zero, COALESCED per-cell pattern. Block = one x-row (128
// threads); thread = one cell. Per replica: load the single bf16x2 uint
// holding this cell's slot (adjacent lanes -> adjacent uints, warp covers
// ~272B = 2-3 lines; x-pair lanes broadcast the same uint). Huber + block
// reduce. __syncthreads (all uint sharing is x-pairs within this row, hence
// within this block) then zero each uint exactly once via the owner rule:
// the lx==0 cell owns it, plus x==0 owns its left-boundary uint (whose lo
// half is padding with no owning thread).
// ---------------------------------------------------------------------------
#define HZ_THREADS 128

__global__ void huber_zero_kernel(float* __restrict__ out) {
    unsigned* __restrict__ gu = reinterpret_cast<unsigned*>(g_rep);
    const int x  = threadIdx.x;          // 0..127, cell x within the row
    const int yy = blockIdx.x & 127;
    const int zz = blockIdx.x >> 7;

    unsigned addr8[8];
    unsigned own = 0;                    // bitmask: reps whose uint I zero
    float v = 0.f;

    #pragma unroll
    for (int rep = 0; rep < 8; ++rep) {
        const int sx = rep & 1, sy = (rep >> 1) & 1, sz = rep >> 2;
        const int lx = (x  ^ sx) & 1;
        const int ly = (yy ^ sy) & 1;
        const int lz = (zz ^ sz) & 1;
        const int bx = (x  - lx + sx + 2) >> 1;
        const int by = (yy - ly + sy + 2) >> 1;
        const int bz = (zz - lz + sz + 2) >> 1;
        const unsigned a = ((unsigned)rep * (unsigned)BRICKS
                          + ((unsigned)bz * RB + by) * RB + bx) * 4u
                         + (unsigned)((lz << 1) | ly);
        const unsigned u = gu[a];
        const __nv_bfloat162 b2 = *reinterpret_cast<const __nv_bfloat162*>(&u);
        v += __bfloat162float(lx ? b2.y : b2.x);
        addr8[rep] = a;
        if (lx == 0 || x == 0) own |= (1u << rep);
    }

    // huber(delta=1)
    const float a = fabsf(v);
    float s = (a <= 1.f) ? 0.5f * v * v : a - 0.5f;

    #pragma unroll
    for (int o = 16; o; o >>= 1) s += __shfl_xor_sync(0xFFFFFFFFu, s, o);

    __shared__ float smem[4];
    const int lane = threadIdx.x & 31;
    const int warp = threadIdx.x >> 5;
    if (lane == 0) smem[warp] = s;
    __syncthreads();                     // also orders all loads before stores
    if (warp == 0 && lane == 0)
        atomicAdd(out, smem[0] + smem[1] + smem[2] + smem[3]);

    // Zero phase: single-owner stores (disjoint addresses, deterministic).
    #pragma unroll
    for (int rep = 0; rep < 8; ++rep)
        if (own & (1u << rep)) gu[addr8[rep]] = 0u;
}

// ---------------------------------------------------------------------------
// Launch: splat -> fused huber+zero
// ---------------------------------------------------------------------------
extern "C" void kernel_launch(void* const* d_in, const int* in_sizes, int n_in,
                              void* d_out, int out_size) {
    const float* pred   = (const float*)d_in[0];  // registration_pred [1,N,3]
    const float* gt     = (const float*)d_in[1];  // registration_gt   [1,N,3]
    const float* coords = (const float*)d_in[2];  // coords            [1,N,3]
    float* out = (float*)d_out;

    const int N = in_sizes[0] / 3;

    {   // splat: one thread per point (pred +1, gt -1); also zeroes *out
        const int threads = 256;
        splat_kernel<<<(N + threads - 1) / threads, threads>>>(
            pred, gt, coords, N, out);
    }
    {   // fused huber gather + reduction + grid re-zero: 1 cell/thread,
        // block = one x-row
        huber_zero_kernel<<<CELLS / HZ_THREADS, HZ_THREADS>>>(out);
    }
}

// round 15
// speedup vs baseline: 1.8897x; 1.2086x over previous
#include <cuda_runtime.h>
#include <cuda_bf16.h>

#define GD 128
#define RB 66                         // brick coords 0..65 cover x0 in [-2..128]
#define BRICKS (RB * RB * RB)         // 287,496 bricks per replica
#define TOTAL_BRICKS (8 * BRICKS)     // 8 parity replicas
#define CELLS (GD * GD * GD)
// Each brick = 2x2x2 cells as bf16 = 16 bytes.
__device__ uint4 g_rep[TOTAL_BRICKS]; // 36.8 MB, zero-initialized at load;
                                      // zero_kernel restores invariant per call.

__device__ __forceinline__ unsigned pack_bf16x2(float lo, float hi) {
    unsigned u;
    asm("cvt.rn.bf16x2.f32 %0, %1, %2;" : "=r"(u) : "f"(hi), "f"(lo));
    return u;
}

__device__ __forceinline__ void red_add_v4_bf16x2(void* addr, unsigned a,
                                                  unsigned b, unsigned c,
                                                  unsigned d) {
    asm volatile("red.global.add.noftz.v4.bf16x2 [%0], {%1, %2, %3, %4};"
                 :: "l"(addr), "r"(a), "r"(b), "r"(c), "r"(d) : "memory");
}

// ---------------------------------------------------------------------------
// One splat = ONE v4.bf16x2 red: replica (x0&1,y0&1,z0&1) makes the 2x2x2
// corner cube one aligned 16B brick. Lane idx = lz*4 + ly*2 + lx.
// ---------------------------------------------------------------------------
__device__ __forceinline__ void splat_one(float cx, float cy, float cz,
                                          float sign) {
    const float x = fmaf(cx, 64.0f, 63.5f);   // ((c+1)*128-1)/2
    const float y = fmaf(cy, 64.0f, 63.5f);
    const float z = fmaf(cz, 64.0f, 63.5f);

    const float x0f = floorf(x), y0f = floorf(y), z0f = floorf(z);
    const float fx = x - x0f, fy = y - y0f, fz = z - z0f;
    int x0 = (int)x0f, y0 = (int)y0f, z0 = (int)z0f;
    // Far-out points clamp into the padded range; OOB corners land in padding
    // slots the huber gather never reads.
    x0 = max(-2, min(128, x0));
    y0 = max(-2, min(128, y0));
    z0 = max(-2, min(128, z0));

    const float wx0 = 1.0f - fx, wx1 = fx;
    const float wy0 = 1.0f - fy, wy1 = fy;
    const float wz0 = (1.0f - fz) * sign, wz1 = fz * sign;

    const int sx = x0 & 1, sy = y0 & 1, sz = z0 & 1;
    const int bx = (x0 + sx + 2) >> 1;
    const int by = (y0 + sy + 2) >> 1;
    const int bz = (z0 + sz + 2) >> 1;
    const int rep = (sz << 2) | (sy << 1) | sx;

    uint4* addr = g_rep + (size_t)rep * BRICKS
                + ((size_t)bz * RB + by) * RB + bx;

    const float a00 = wx0 * wy0, a10 = wx1 * wy0;
    const float a01 = wx0 * wy1, a11 = wx1 * wy1;

    red_add_v4_bf16x2(addr,
        pack_bf16x2(a00 * wz0, a10 * wz0),
        pack_bf16x2(a01 * wz0, a11 * wz0),
        pack_bf16x2(a00 * wz1, a10 * wz1),
        pack_bf16x2(a01 * wz1, a11 * wz1));
}

// ---------------------------------------------------------------------------
// Splat: ONE point per thread (proven best occupancy/latency-hiding shape).
// ---------------------------------------------------------------------------
__global__ void splat_kernel(const float* __restrict__ pred,
                             const float* __restrict__ gt,
                             const float* __restrict__ coords,
                             int N, float* __restrict__ out) {
    const int p = blockIdx.x * blockDim.x + threadIdx.x;
    if (p == 0) *out = 0.f;      // huber (next kernel) accumulates into out
    if (p >= N) return;

    const float cx = coords[3 * p + 0];
    const float cy = coords[3 * p + 1];
    const float cz = coords[3 * p + 2];
    const float px = pred[3 * p + 0];
    const float py = pred[3 * p + 1];
    const float pz = pred[3 * p + 2];
    const float gx = gt[3 * p + 0];
    const float gy = gt[3 * p + 1];
    const float gz = gt[3 * p + 2];

    splat_one(cx + px, cy + py, cz + pz,  1.0f);
    splat_one(cx + gx, cy + gy, cz + gz, -1.0f);
}

// ---------------------------------------------------------------------------
// Huber: PAIR-granularity gather. One work item = an x-pair (cells 2px,2px+1).
//  sx=0 replicas: both cells share ONE uint (lo=even cell, hi=odd cell).
//  sx=1 replicas: even cell = hi of uint at brick px+1, odd = lo at px+2.
// -> 12 coalesced 4B loads per 2 cells (vs 16 2B loads per-cell).
// Thread handles 2 pairs (strided) -> 24 independent loads.
// ---------------------------------------------------------------------------
#define HUB_BLOCKS 2048
#define HUB_THREADS 256
#define PAIRS (CELLS / 2)                        // 1,048,576
#define HUB_STRIDE (HUB_BLOCKS * HUB_THREADS)    // 524,288; x2 = PAIRS

__device__ __forceinline__ void huber_pair(const unsigned* __restrict__ gu,
                                           int q, float& s) {
    const int px = q & 63;            // pair x: cells 2px, 2px+1
    const int yy = (q >> 6) & 127;
    const int zz = q >> 13;

    float v0 = 0.f, v1 = 0.f;
    #pragma unroll
    for (int rep = 0; rep < 8; ++rep) {
        const int sx = rep & 1, sy = (rep >> 1) & 1, sz = rep >> 2;
        const int ly = (yy ^ sy) & 1;
        const int lz = (zz ^ sz) & 1;
        const int by = (yy - ly + sy + 2) >> 1;
        const int bz = (zz - lz + sz + 2) >> 1;
        const unsigned rowbase =
            ((unsigned)rep * (unsigned)BRICKS
             + ((unsigned)bz * RB + by) * RB) * 4u
            + (unsigned)((lz << 1) | ly);

        if (sx == 0) {
            const unsigned u = gu[rowbase + (unsigned)(px + 1) * 4u];
            const __nv_bfloat162 b2 =
                *reinterpret_cast<const __nv_bfloat162*>(&u);
            v0 += __bfloat162float(b2.x);
            v1 += __bfloat162float(b2.y);
        } else {
            const unsigned ua = gu[rowbase + (unsigned)(px + 1) * 4u];
            const unsigned ub = gu[rowbase + (unsigned)(px + 2) * 4u];
            const __nv_bfloat162 ba =
                *reinterpret_cast<const __nv_bfloat162*>(&ua);
            const __nv_bfloat162 bb =
                *reinterpret_cast<const __nv_bfloat162*>(&ub);
            v0 += __bfloat162float(ba.y);
            v1 += __bfloat162float(bb.x);
        }
    }

    float a;
    a = fabsf(v0); s += (a <= 1.f) ? 0.5f * v0 * v0 : a - 0.5f;
    a = fabsf(v1); s += (a <= 1.f) ? 0.5f * v1 * v1 : a - 0.5f;
}

__global__ void huber_kernel(float* __restrict__ out) {
    const unsigned* __restrict__ gu =
        reinterpret_cast<const unsigned*>(g_rep);
    const int t = blockIdx.x * HUB_THREADS + threadIdx.x;

    float s = 0.f;
    huber_pair(gu, t, s);
    huber_pair(gu, t + HUB_STRIDE, s);

    #pragma unroll
    for (int o = 16; o; o >>= 1) s += __shfl_xor_sync(0xFFFFFFFFu, s, o);

    __shared__ float smem[8];
    const int lane = threadIdx.x & 31;
    const int warp = threadIdx.x >> 5;
    if (lane == 0) smem[warp] = s;
    __syncthreads();

    if (warp == 0) {
        s = (lane < (HUB_THREADS >> 5)) ? smem[lane] : 0.f;
        #pragma unroll
        for (int o = 4; o; o >>= 1) s += __shfl_xor_sync(0xFFFFFFFFu, s, o);
        if (lane == 0) atomicAdd(out, s);
    }
}

// ---------------------------------------------------------------------------
// Zero the replica bricks (4 bricks = 64B per thread).
// ---------------------------------------------------------------------------
__global__ void zero_kernel() {
    const int i = (blockIdx.x * blockDim.x + threadIdx.x) * 4;
    if (i + 4 <= TOTAL_BRICKS) {
        const uint4 z = make_uint4(0u, 0u, 0u, 0u);
        g_rep[i] = z; g_rep[i+1] = z; g_rep[i+2] = z; g_rep[i+3] = z;
    } else {
        for (int k = i; k < TOTAL_BRICKS; ++k)
            g_rep[k] = make_uint4(0u, 0u, 0u, 0u);
    }
}

// ---------------------------------------------------------------------------
// Launch: splat -> huber -> zero
// ---------------------------------------------------------------------------
extern "C" void kernel_launch(void* const* d_in, const int* in_sizes, int n_in,
                              void* d_out, int out_size) {
    const float* pred   = (const float*)d_in[0];  // registration_pred [1,N,3]
    const float* gt     = (const float*)d_in[1];  // registration_gt   [1,N,3]
    const float* coords = (const float*)d_in[2];  // coords            [1,N,3]
    float* out = (float*)d_out;

    const int N = in_sizes[0] / 3;

    {   // splat: one thread per point (pred +1, gt -1); also zeroes *out
        const int threads = 256;
        splat_kernel<<<(N + threads - 1) / threads, threads>>>(
            pred, gt, coords, N, out);
    }
    {   // huber gather + reduction: 2 x-pairs (4 cells) per thread
        huber_kernel<<<HUB_BLOCKS, HUB_THREADS>>>(out);
    }
    {   // reset replica bricks for next replay
        const int threads = 256;
        const int nt = (TOTAL_BRICKS + 3) / 4;
        zero_kernel<<<(nt + threads - 1) / threads, threads>>>();
    }
}